// round 4
// baseline (speedup 1.0000x reference)
#include <cuda_runtime.h>
#include <cuda_fp16.h>

#define N_NODES 1000000
#define N_EDGES 8000000
#define EMB 64
#define CDIM 32
#define NEG 0.01f
#define EPS 1e-10f

// ---------------- scratch (device globals; no runtime allocation) ----------------
__device__ __align__(128) __half g_h0[(size_t)N_NODES * CDIM]; // channel-0 features fp16 (64 MB, L2-resident)
__device__ __align__(128) __half g_h1[(size_t)N_NODES * CDIM]; // channel-1 features fp16 (64 MB, L2-resident)
__device__ int   g_cnt[N_NODES];               // per-row edge counts
__device__ int   g_start[N_NODES];             // CSR row starts (exclusive scan)
__device__ int   g_cursor[N_NODES];            // scatter cursors
__device__ int   g_perm[N_EDGES];              // col index grouped by row
__device__ int   g_bsum[1024];                 // scan block sums

static __device__ __forceinline__ float lrelu(float x) {
    return fmaxf(x, NEG * x);
}

// ---------------- 0: zero counts ----------------
__global__ void zero_kernel() {
    int i = blockIdx.x * blockDim.x + threadIdx.x;
    if (i < N_NODES) g_cnt[i] = 0;
}

// ---------------- 1: projection  h = lrelu(ego @ Wcomb + b), split fp16 tables ----------------
__global__ __launch_bounds__(256) void proj_kernel(const float* __restrict__ ego,
                                                   const float* __restrict__ W,
                                                   const float* __restrict__ b) {
    __shared__ __align__(16) float Wsh[EMB][EMB];
    __shared__ float bsh[EMB];
    int tid = threadIdx.x;
    for (int i = tid; i < 2 * 64 * 32; i += blockDim.x) {
        int c = i >> 11;
        int k = (i >> 5) & 63;
        int j = i & 31;
        Wsh[k][c * 32 + j] = W[i];
    }
    if (tid < EMB) bsh[tid] = b[tid];   // b is [2][1][32] contiguous == [64]
    __syncthreads();

    int row = blockIdx.x * blockDim.x + tid;
    if (row >= N_NODES) return;

    const float4* egorow = (const float4*)(ego + (size_t)row * EMB);

    unsigned long long acc2[32];
#pragma unroll
    for (int m = 0; m < 32; m++) {
        float lo = bsh[2 * m], hi = bsh[2 * m + 1];
        asm("mov.b64 %0, {%1, %2};" : "=l"(acc2[m]) : "f"(lo), "f"(hi));
    }

#pragma unroll 1
    for (int kc = 0; kc < 4; kc++) {
        float4 e4[4];
#pragma unroll
        for (int q = 0; q < 4; q++) e4[q] = egorow[kc * 4 + q];
#pragma unroll
        for (int kq = 0; kq < 16; kq++) {
            float ev = ((const float*)e4)[kq];
            unsigned long long ep;
            asm("mov.b64 %0, {%1, %1};" : "=l"(ep) : "f"(ev));
            int k = kc * 16 + kq;
            const ulonglong2* wrow = (const ulonglong2*)(&Wsh[k][0]);
#pragma unroll
            for (int q = 0; q < 16; q++) {
                ulonglong2 w = wrow[q];   // LDS.128 broadcast
                asm("fma.rn.f32x2 %0, %1, %2, %0;" : "+l"(acc2[2 * q])     : "l"(ep), "l"(w.x));
                asm("fma.rn.f32x2 %0, %1, %2, %0;" : "+l"(acc2[2 * q + 1]) : "l"(ep), "l"(w.y));
            }
        }
    }

    // acc2[m] holds output dims (2m, 2m+1): m 0..15 -> channel 0, m 16..31 -> channel 1
    uint4* h0 = (uint4*)(g_h0 + (size_t)row * CDIM);
    uint4* h1 = (uint4*)(g_h1 + (size_t)row * CDIM);
#pragma unroll
    for (int q = 0; q < 4; q++) {
        unsigned r0[4], r1[4];
#pragma unroll
        for (int t = 0; t < 4; t++) {
            float a, bb;
            asm("mov.b64 {%0, %1}, %2;" : "=f"(a), "=f"(bb) : "l"(acc2[4 * q + t]));
            __half2 h2 = __floats2half2_rn(lrelu(a), lrelu(bb));
            r0[t] = *(unsigned*)&h2;
            asm("mov.b64 {%0, %1}, %2;" : "=f"(a), "=f"(bb) : "l"(acc2[16 + 4 * q + t]));
            h2 = __floats2half2_rn(lrelu(a), lrelu(bb));
            r1[t] = *(unsigned*)&h2;
        }
        h0[q] = make_uint4(r0[0], r0[1], r0[2], r0[3]);
        h1[q] = make_uint4(r1[0], r1[1], r1[2], r1[3]);
    }
}

// ---------------- 2: histogram of destination rows ----------------
__global__ void hist_kernel(const int* __restrict__ row) {
    int e = blockIdx.x * blockDim.x + threadIdx.x;
    if (e < N_EDGES) atomicAdd(&g_cnt[row[e]], 1);
}

// ---------------- 3-5: exclusive scan of counts ----------------
__global__ void scan1_kernel() {
    __shared__ int wsum[8];
    int tid = threadIdx.x;
    int lane = tid & 31, wid = tid >> 5;
    int base = blockIdx.x * 1024 + tid * 4;
    int v[4];
#pragma unroll
    for (int i = 0; i < 4; i++) v[i] = (base + i < N_NODES) ? g_cnt[base + i] : 0;
    int s = v[0] + v[1] + v[2] + v[3];
    int x = s;
#pragma unroll
    for (int o = 1; o < 32; o <<= 1) {
        int y = __shfl_up_sync(0xffffffffu, x, o);
        if (lane >= o) x += y;
    }
    if (lane == 31) wsum[wid] = x;
    __syncthreads();
    if (wid == 0) {
        int w = (lane < 8) ? wsum[lane] : 0;
#pragma unroll
        for (int o = 1; o < 8; o <<= 1) {
            int y = __shfl_up_sync(0xffffffffu, w, o);
            if (lane >= o) w += y;
        }
        if (lane < 8) wsum[lane] = w;
        if (lane == 7) g_bsum[blockIdx.x] = w;
    }
    __syncthreads();
    int excl = x - s + (wid > 0 ? wsum[wid - 1] : 0);
#pragma unroll
    for (int i = 0; i < 4; i++) {
        if (base + i < N_NODES) g_start[base + i] = excl;
        excl += v[i];
    }
}

__global__ void scan2_kernel(int nb) {
    __shared__ int wsum[32];
    int tid = threadIdx.x, lane = tid & 31, wid = tid >> 5;
    int s = (tid < nb) ? g_bsum[tid] : 0;
    int x = s;
#pragma unroll
    for (int o = 1; o < 32; o <<= 1) {
        int y = __shfl_up_sync(0xffffffffu, x, o);
        if (lane >= o) x += y;
    }
    if (lane == 31) wsum[wid] = x;
    __syncthreads();
    if (wid == 0) {
        int w = wsum[lane];
#pragma unroll
        for (int o = 1; o < 32; o <<= 1) {
            int y = __shfl_up_sync(0xffffffffu, w, o);
            if (lane >= o) w += y;
        }
        wsum[lane] = w;
    }
    __syncthreads();
    int excl = x - s + (wid > 0 ? wsum[wid - 1] : 0);
    if (tid < nb) g_bsum[tid] = excl;
}

__global__ void scan3_kernel() {
    int i = blockIdx.x * blockDim.x + threadIdx.x;
    if (i < N_NODES) {
        int s = g_start[i] + g_bsum[i >> 10];
        g_start[i]  = s;
        g_cursor[i] = s;
    }
}

// ---------------- 6: scatter col indices grouped by row ----------------
__global__ void scatter_kernel(const int* __restrict__ row, const int* __restrict__ col) {
    int e = blockIdx.x * blockDim.x + threadIdx.x;
    if (e < N_EDGES) {
        int p = atomicAdd(&g_cursor[row[e]], 1);
        g_perm[p] = col[e];
    }
}

// ---------------- 7: per-channel fused edge softmax + aggregation ----------------
// One warp per destination row; 4 edges per iteration in 8-lane subgroups.
// Channel table selected INSIDE the kernel (device-global addresses are not
// valid as host-side kernel arguments).
__global__ __launch_bounds__(256) void agg_kernel(int channel, float* __restrict__ out) {
    const __half* __restrict__ htab = channel ? g_h1 : g_h0;
    float* __restrict__ out_base = out + channel * CDIM;

    int lane = threadIdx.x & 31;
    int row = (blockIdx.x * blockDim.x + threadIdx.x) >> 5;
    if (row >= N_NODES) return;
    int sub = lane >> 3;   // edge slot 0..3
    int s   = lane & 7;    // dim slot (4 dims each)

    int start = g_start[row];
    int cnt   = g_cnt[row];

    float hr[4];
    {
        uint2 v = *(const uint2*)(htab + (size_t)row * CDIM + s * 4);
        float2 fa = __half22float2(*(__half2*)&v.x);
        float2 fb = __half22float2(*(__half2*)&v.y);
        hr[0] = fa.x; hr[1] = fa.y; hr[2] = fb.x; hr[3] = fb.y;
    }

    float acc[4] = {0.f, 0.f, 0.f, 0.f};
    float accD = 0.f;

    for (int base = 0; base < cnt; base += 4) {
        int i = base + sub;
        bool valid = i < cnt;
        float hc[4] = {0.f, 0.f, 0.f, 0.f};
        float p = 0.f;
        if (valid) {
            int c = __ldcs(&g_perm[start + i]);
            uint2 v = *(const uint2*)(htab + (size_t)c * CDIM + s * 4);
            float2 fa = __half22float2(*(__half2*)&v.x);
            float2 fb = __half22float2(*(__half2*)&v.y);
            hc[0] = fa.x; hc[1] = fa.y; hc[2] = fb.x; hc[3] = fb.y;
            p = hr[0] * hc[0] + hr[1] * hc[1] + hr[2] * hc[2] + hr[3] * hc[3];
        }
        p += __shfl_xor_sync(0xffffffffu, p, 1);
        p += __shfl_xor_sync(0xffffffffu, p, 2);
        p += __shfl_xor_sync(0xffffffffu, p, 4);
        if (valid) {
            float ex = __expf(lrelu(p));
            accD += ex;
#pragma unroll
            for (int q = 0; q < 4; q++) acc[q] = fmaf(ex, hc[q], acc[q]);
        }
    }

    // fold the 4 edge subgroups
#pragma unroll
    for (int q = 0; q < 4; q++) {
        acc[q] += __shfl_xor_sync(0xffffffffu, acc[q], 8);
        acc[q] += __shfl_xor_sync(0xffffffffu, acc[q], 16);
    }
    accD += __shfl_xor_sync(0xffffffffu, accD, 8);
    accD += __shfl_xor_sync(0xffffffffu, accD, 16);

    if (sub == 0) {
        float inv = 1.f / (accD + EPS);
        float4 o = make_float4(acc[0] * inv, acc[1] * inv, acc[2] * inv, acc[3] * inv);
        __stcs((float4*)(out_base + (size_t)row * EMB + s * 4), o);
    }
}

// ---------------- launcher ----------------
extern "C" void kernel_launch(void* const* d_in, const int* in_sizes, int n_in,
                              void* d_out, int out_size) {
    const float* ego = (const float*)d_in[0];
    const float* W   = (const float*)d_in[1];
    const float* b   = (const float*)d_in[2];
    const int* rowi  = (const int*)d_in[3];
    const int* coli  = (const int*)d_in[4];
    float* out = (float*)d_out;

    const int NB_NODES = (N_NODES + 255) / 256;   // 3907
    const int NB_EDGES = (N_EDGES + 255) / 256;   // 31250
    const int NB_SCAN  = (N_NODES + 1023) / 1024; // 977
    const int NB_AGG   = (N_NODES * 32 + 255) / 256; // warp per row

    zero_kernel<<<NB_NODES, 256>>>();
    proj_kernel<<<NB_NODES, 256>>>(ego, W, b);
    hist_kernel<<<NB_EDGES, 256>>>(rowi);
    scan1_kernel<<<NB_SCAN, 256>>>();
    scan2_kernel<<<1, 1024>>>(NB_SCAN);
    scan3_kernel<<<NB_NODES, 256>>>();
    scatter_kernel<<<NB_EDGES, 256>>>(rowi, coli);
    agg_kernel<<<NB_AGG, 256>>>(0, out);   // channel 0 -> cols [0,32)
    agg_kernel<<<NB_AGG, 256>>>(1, out);   // channel 1 -> cols [32,64)
}